// round 15
// baseline (speedup 1.0000x reference)
#include <cuda_runtime.h>
#include <math.h>

#define NB 2
#define NN 20001
#define NE 500000
#define MAXL2 4096
#define MAXNODES (MAXL2 + 1)
#define MAXTASK (NB * MAXNODES)
#define MAXE1 65536
#define MAXEPN 1024
#define CH2 1024
#define GRID 148
#define NFOLD 3
#define NSCAN (GRID - NFOLD)
#define TPB 1024
#define NQ (NE / 4)
#define NG (NQ / 4)
#define BMW 640
#define SCALEF 22.62741699796952f
#define INV_SCALEF (1.0f / 22.62741699796952f)
#define LN_EPS 1e-6f
#define ALPHA 0.2f

#define PF_L2(p) asm volatile("prefetch.global.L2 [%0];" :: "l"(p))

// ---------------- scratch (device globals; zero-init on load) ----------------
__device__ int   g_map[NB * NN];
__device__ int   g_nodes[NB * MAXNODES];
__device__ int   g_nn[NB];
__device__ int   g_c1[NB];
__device__ int   g_c2[NB];
__device__ volatile int g_bar;
__device__ int   g_done;
__device__ volatile int g_pc[NB];
__device__ int   g_l2dst[NB * MAXL2];
__device__ int   g_e1src[NB * MAXE1];
__device__ int   g_e1dst[NB * MAXE1];
__device__ float g_u1[4 * 256], g_v1[4 * 256], g_c1s[4], g_d1s[4];
__device__ float g_u2[4 * 512], g_v2[4 * 512], g_c2s[4], g_d2s[4];
__device__ __align__(16) float g_agg1[(size_t)MAXTASK * 1024];
__device__ float g_rs1v[MAXTASK * 4];
__device__ float g_hcat[(size_t)NB * MAXNODES * 512];
__device__ float g_p[NB * 512];

// ---------------- helpers ----------------
__device__ __forceinline__ float warp_sum(float v) {
#pragma unroll
    for (int o = 16; o > 0; o >>= 1) v += __shfl_xor_sync(0xffffffffu, v, o);
    return v;
}

// dual interleaved block sum; sm >= 66 floats
__device__ void block_sum2(float& v0, float& v1, float* sm) {
    int tid = threadIdx.x, w = tid >> 5, l = tid & 31, nw = blockDim.x >> 5;
#pragma unroll
    for (int o = 16; o > 0; o >>= 1) {
        v0 += __shfl_xor_sync(0xffffffffu, v0, o);
        v1 += __shfl_xor_sync(0xffffffffu, v1, o);
    }
    if (l == 0) { sm[w] = v0; sm[32 + w] = v1; }
    __syncthreads();
    if (w == 0) {
        float r0 = (l < nw) ? sm[l] : 0.f;
        float r1 = (l < nw) ? sm[32 + l] : 0.f;
#pragma unroll
        for (int o = 16; o > 0; o >>= 1) {
            r0 += __shfl_xor_sync(0xffffffffu, r0, o);
            r1 += __shfl_xor_sync(0xffffffffu, r1, o);
        }
        if (l == 0) { sm[64] = r0; sm[65] = r1; }
    }
    __syncthreads();
    v0 = sm[64]; v1 = sm[65];
    __syncthreads();
}

__device__ __forceinline__ float lrelu_scale_exp(float s) {
    float t = (s > 0.f) ? s : (ALPHA * s);
    return __expf(t * INV_SCALEF);
}

__device__ __forceinline__ void map_insert(int b, int node) {
    if (atomicCAS(&g_map[b * NN + node], 0, -1) == 0) {
        int q = atomicAdd(&g_nn[b], 1);
        if (q < MAXNODES) {
            g_nodes[b * MAXNODES + q] = node;
            g_map[b * NN + node] = q + 1;
        }
    }
}

__device__ __forceinline__ void pf_embed_row(const float* embed, int node) {
    const float* er = embed + (size_t)node * 256;
#pragma unroll
    for (int q = 0; q < 8; q++) PF_L2(er + 32 * q);
}

__device__ __forceinline__ void grid_sync(int target) {
    __syncthreads();
    __threadfence();
    if (threadIdx.x == 0) {
        atomicAdd((int*)&g_bar, 1);
        while (g_bar < target) { }
    }
    __syncthreads();
}

// =================== THE kernel: everything in one launch ====================
__global__ void __launch_bounds__(TPB) kAll(
    const int* __restrict__ ei, const int* __restrict__ eo,
    const float* __restrict__ embed,
    const float* __restrict__ W1, const float* __restrict__ b1,
    const float* __restrict__ a1, const float* __restrict__ g1,
    const float* __restrict__ bn1,
    const float* __restrict__ W2, const float* __restrict__ b2,
    const float* __restrict__ a2, const float* __restrict__ g2,
    const float* __restrict__ bn2,
    const float* __restrict__ Vw, const float* __restrict__ Vb,
    float* __restrict__ out) {

    __shared__ int   s_dst[MAXEPN];
    __shared__ __align__(16) float s_ev[MAXEPN * 4];   // also: s_agg4 in 2b
    __shared__ __align__(16) float s_agg[2048];        // also: s_out4 in 2b
    __shared__ float s_x[512];
    __shared__ float s_sA[4];
    __shared__ float s_rs[4];
    __shared__ float s_rs4[16];
    __shared__ float s_red[66];
    __shared__ int   s_m;
    __shared__ unsigned int s_bm[NB * BMW];

    int t = threadIdx.x, lane = t & 31, w = t >> 5;
    int bx = blockIdx.x;

    // ---------- phase 0: folds (last 3 blocks) || edge_out scan (rest) -------
    if (bx >= NSCAN) {
        int fg = (bx - NSCAN) * TPB + t;
        if (fg < 1024) {
            int h = fg >> 8, k = fg & 255;
            float au = 0.f, av = 0.f;
#pragma unroll 32
            for (int j = 0; j < 128; j++) {
                float wv = W1[(h * 128 + j) * 256 + k];
                au += a1[h * 256 + j] * wv;
                av += a1[h * 256 + 128 + j] * wv;
            }
            g_u1[h * 256 + k] = au;
            g_v1[h * 256 + k] = av;
        } else if (fg < 3072) {
            int g2i = fg - 1024;
            int h = g2i >> 9, k = g2i & 511;
            float au = 0.f, av = 0.f;
#pragma unroll 32
            for (int j = 0; j < 128; j++) {
                float wv = W2[(h * 128 + j) * 512 + k];
                au += a2[h * 256 + j] * wv;
                av += a2[h * 256 + 128 + j] * wv;
            }
            g_u2[h * 512 + k] = au;
            g_v2[h * 512 + k] = av;
        }
        if (fg < 4) {
            int h = fg;
            float c1v = 0.f, d1v = 0.f, c2v = 0.f, d2v = 0.f;
            for (int j = 0; j < 128; j++) {
                c1v += a1[h * 256 + j] * b1[h * 128 + j];
                d1v += a1[h * 256 + 128 + j] * b1[h * 128 + j];
                c2v += a2[h * 256 + j] * b2[h * 128 + j];
                d2v += a2[h * 256 + 128 + j] * b2[h * 128 + j];
            }
            g_c1s[h] = c1v; g_d1s[h] = d1v; g_c2s[h] = c2v; g_d2s[h] = d2v;
        }
        if (fg < NB) {
            map_insert(fg, NN - 1);
            pf_embed_row(embed, NN - 1);
        }
    } else {
        int g = bx * TPB + t;
        if (g < NB * NG) {
            int b = (g >= NG) ? 1 : 0;
            int gg = g - b * NG;
            const int4* p = (const int4*)(eo + (size_t)(2 * b) * NE) + 4 * gg;
            int4 v0 = p[0], v1 = p[1], v2 = p[2], v3 = p[3];
            int base = gg * 16;
            const int* dstrow = eo + (size_t)(2 * b + 1) * NE;
            int sv[16] = {v0.x, v0.y, v0.z, v0.w, v1.x, v1.y, v1.z, v1.w,
                          v2.x, v2.y, v2.z, v2.w, v3.x, v3.y, v3.z, v3.w};
#pragma unroll
            for (int c = 0; c < 16; c++) {
                if (sv[c] == NN - 1) {
                    int dst = dstrow[base + c];
                    int pp = atomicAdd(&g_c2[b], 1);
                    if (pp < MAXL2) g_l2dst[b * MAXL2 + pp] = dst;
                    map_insert(b, dst);
                    pf_embed_row(embed, dst);
                }
            }
        }
    }

    grid_sync(1 * GRID);

    // ---------- bitmap of node set ----------
    for (int i = t; i < NB * BMW; i += TPB) s_bm[i] = 0u;
    __syncthreads();
    {
        int nn0 = min(g_nn[0], MAXNODES);
        int nn1 = min(g_nn[1], MAXNODES);
        for (int i = t; i < nn0; i += TPB) {
            int node = g_nodes[0 * MAXNODES + i];
            atomicOr(&s_bm[0 * BMW + (node >> 5)], 1u << (node & 31));
        }
        for (int i = t; i < nn1; i += TPB) {
            int node = g_nodes[1 * MAXNODES + i];
            atomicOr(&s_bm[1 * BMW + (node >> 5)], 1u << (node & 31));
        }
    }
    __syncthreads();

    // ---------- phase 1: edge_in scan ----------
    {
        int g = bx * TPB + t;
        if (g < NB * NG) {
            int b = (g >= NG) ? 1 : 0;
            int gg = g - b * NG;
            const int4* p = (const int4*)(ei + (size_t)(2 * b) * NE) + 4 * gg;
            int4 v0 = p[0], v1 = p[1], v2 = p[2], v3 = p[3];
            int base = gg * 16;
            const int* dstrow = ei + (size_t)(2 * b + 1) * NE;
            const unsigned int* bm = &s_bm[b * BMW];
            int sv[16] = {v0.x, v0.y, v0.z, v0.w, v1.x, v1.y, v1.z, v1.w,
                          v2.x, v2.y, v2.z, v2.w, v3.x, v3.y, v3.z, v3.w};
#pragma unroll
            for (int c = 0; c < 16; c++) {
                int src = sv[c];
                if ((bm[src >> 5] >> (src & 31)) & 1u) {
                    int m = g_map[b * NN + src];
                    if (m > 0) {
                        int dst = dstrow[base + c];
                        int pp = atomicAdd(&g_c1[b], 1);
                        if (pp < MAXE1) {
                            g_e1src[b * MAXE1 + pp] = m - 1;
                            g_e1dst[b * MAXE1 + pp] = dst;
                        }
                        pf_embed_row(embed, dst);
                    }
                }
            }
        }
    }

    grid_sync(2 * GRID);

    int nnr0 = min(g_nn[0], MAXNODES);
    int nnr1 = min(g_nn[1], MAXNODES);
    int ntask = nnr0 + nnr1;

    // ---------- phase 2a: attention + aggregation per node (no W1) ----------
    for (int task = bx; task < ntask; task += GRID) {
        int b = (task >= nnr0) ? 1 : 0;
        int ln = task - b * nnr0;
        int cnt = min(g_c1[b], MAXE1);

        if (t == 0) s_m = 0;
        __syncthreads();
        for (int i = t; i < cnt; i += TPB)
            if (g_e1src[b * MAXE1 + i] == ln) {
                int p = atomicAdd(&s_m, 1);
                if (p < MAXEPN) s_dst[p] = g_e1dst[b * MAXE1 + i];
            }
        int node = g_nodes[b * MAXNODES + ln];
        if (t < 256) s_x[t] = embed[(size_t)node * 256 + t];
        __syncthreads();
        int m = min(s_m, MAXEPN);

        if (w < 4) {
            float a = 0.f;
#pragma unroll
            for (int q = 0; q < 8; q++) a += s_x[lane + 32 * q] * g_u1[w * 256 + lane + 32 * q];
            a = warp_sum(a);
            if (lane == 0) s_sA[w] = a + g_c1s[w];
        }
        __syncthreads();

        for (int e = w; e < m; e += 32) {
            const float* er = embed + (size_t)s_dst[e] * 256;
            float emb[8];
#pragma unroll
            for (int q = 0; q < 8; q++) emb[q] = er[lane + 32 * q];
            float a4[4];
#pragma unroll
            for (int h = 0; h < 4; h++) {
                float a = 0.f;
#pragma unroll
                for (int q = 0; q < 8; q++) a += emb[q] * g_v1[h * 256 + lane + 32 * q];
                a4[h] = a;
            }
#pragma unroll
            for (int o = 16; o > 0; o >>= 1) {
#pragma unroll
                for (int h = 0; h < 4; h++) a4[h] += __shfl_xor_sync(0xffffffffu, a4[h], o);
            }
            float sel = (lane == 0) ? a4[0] : (lane == 1) ? a4[1] : (lane == 2) ? a4[2] : a4[3];
            if (lane < 4) s_ev[e * 4 + lane] = lrelu_scale_exp(s_sA[lane] + sel + g_d1s[lane]);
        }
        __syncthreads();

        if (t < 256) {
            float a0 = 0.f, a1v = 0.f, a2v = 0.f, a3v = 0.f;
#pragma unroll 8
            for (int e = 0; e < m; e++) {
                float x = embed[(size_t)s_dst[e] * 256 + t];
                a0  += s_ev[e * 4 + 0] * x;
                a1v += s_ev[e * 4 + 1] * x;
                a2v += s_ev[e * 4 + 2] * x;
                a3v += s_ev[e * 4 + 3] * x;
            }
            float* ag = g_agg1 + (size_t)task * 1024;
            ag[0 * 256 + t] = a0;
            ag[1 * 256 + t] = a1v;
            ag[2 * 256 + t] = a2v;
            ag[3 * 256 + t] = a3v;
        } else if (w >= 28) {
            int h = w - 28;
            float r = 0.f;
            for (int e = lane; e < m; e += 32) r += s_ev[e * 4 + h];
            r = warp_sum(r);
            if (lane == 0) g_rs1v[task * 4 + h] = r;
        }
        __syncthreads();
    }

    grid_sync(3 * GRID);

    // ---------- phase 2b: projection (4 tasks/block, W1 amortized) + LN ------
    {
        float* s_agg4 = s_ev;    // 4 x 1024 floats
        float* s_out4 = s_agg;   // 4 x 512 floats
        int ngrp = (ntask + 3) >> 2;
        for (int grp = bx; grp < ngrp; grp += GRID) {
            int t0 = grp * 4;
            int ntt = min(4, ntask - t0);
            for (int k = t; k < ntt * 1024; k += TPB)
                s_agg4[k] = g_agg1[(size_t)(t0 + (k >> 10)) * 1024 + (k & 1023)];
            if (t < ntt * 4) s_rs4[t] = g_rs1v[t0 * 4 + t];
            __syncthreads();

            // warp per row, 16 rows/warp, 4 tasks interleaved per row
#pragma unroll 2
            for (int i = 0; i < 16; i++) {
                int r = w + 32 * i;
                int h = r >> 7;
                const float4* wr = (const float4*)(W1 + (size_t)r * 256);
                float4 w0 = wr[lane], w1 = wr[lane + 32];
                float acc[4];
#pragma unroll
                for (int tt = 0; tt < 4; tt++) {
                    const float4* ag = (const float4*)(s_agg4 + tt * 1024 + h * 256);
                    float4 a0 = ag[lane], a1 = ag[lane + 32];
                    acc[tt] = w0.x * a0.x + w0.y * a0.y + w0.z * a0.z + w0.w * a0.w
                            + w1.x * a1.x + w1.y * a1.y + w1.z * a1.z + w1.w * a1.w;
                }
#pragma unroll
                for (int o = 16; o > 0; o >>= 1) {
#pragma unroll
                    for (int tt = 0; tt < 4; tt++)
                        acc[tt] += __shfl_xor_sync(0xffffffffu, acc[tt], o);
                }
                float sel = (lane == 0) ? acc[0] : (lane == 1) ? acc[1]
                          : (lane == 2) ? acc[2] : acc[3];
                if (lane < 4 && lane < ntt) {
                    float rs = s_rs4[lane * 4 + h];
                    float rsp = (rs == 0.f) ? 1.f : rs;
                    s_out4[lane * 512 + r] = (sel + rs * b1[r]) / rsp;
                }
            }
            __syncthreads();

            // LN + elu: 2 tasks concurrently (threads split in halves)
#pragma unroll
            for (int pp = 0; pp < 2; pp++) {
                int tt = pp * 2 + (t >> 9);
                int idx = t & 511;
                float val = (tt < ntt) ? s_out4[tt * 512 + idx] : 0.f;
                float v0 = val, v1 = val * val;
#pragma unroll
                for (int o = 16; o > 0; o >>= 1) {
                    v0 += __shfl_xor_sync(0xffffffffu, v0, o);
                    v1 += __shfl_xor_sync(0xffffffffu, v1, o);
                }
                if (lane == 0) { s_red[w] = v0; s_red[32 + w] = v1; }
                __syncthreads();
                if (w == 0 || w == 16) {
                    int base = (w == 0) ? 0 : 16;
                    float r0 = (lane < 16) ? s_red[base + lane] : 0.f;
                    float r1 = (lane < 16) ? s_red[32 + base + lane] : 0.f;
#pragma unroll
                    for (int o = 16; o > 0; o >>= 1) {
                        r0 += __shfl_xor_sync(0xffffffffu, r0, o);
                        r1 += __shfl_xor_sync(0xffffffffu, r1, o);
                    }
                    if (lane == 0) { s_red[64 - base / 8] = r0; s_red[65 - base / 8 + 0] = r1; }
                }
                __syncthreads();
                // NOTE: s_red[64],[65] for half A (w==0 wrote 64,65); half B (w==16): 62,63
                float sum, sumsq;
                if ((t >> 9) == 0) { sum = s_red[64]; sumsq = s_red[65]; }
                else               { sum = s_red[62]; sumsq = s_red[63]; }
                if (tt < ntt) {
                    float mn = sum * (1.f / 512.f);
                    float var = (sumsq - 512.f * mn * mn) * (1.f / 511.f);
                    var = fmaxf(var, 0.f);
                    float stdv = sqrtf(var);
                    float y = g1[idx] * (val - mn) / (stdv + LN_EPS) + bn1[idx];
                    int task = t0 + tt;
                    int bb = (task >= nnr0) ? 1 : 0;
                    int ln = task - bb * nnr0;
                    g_hcat[((size_t)bb * MAXNODES + ln) * 512 + idx] = (y > 0.f) ? y : expm1f(y);
                }
                __syncthreads();
            }
        }
    }

    grid_sync(4 * GRID);

    // ---------- phase 3: layer-2 (blocks 0-31) + head via 16-count spin ------
    if (bx < 32) {
        int b = bx & 1;
        int chunk = bx >> 1;
        int cnt = min(g_c2[b], MAXL2);
        int ln0 = g_map[b * NN + (NN - 1)] - 1;
        if (ln0 < 0) ln0 = 0;

        if (t < 512) s_x[t] = g_hcat[((size_t)b * MAXNODES + ln0) * 512 + t];
        if (t < 4) s_rs[t] = 0.f;
        __syncthreads();

        if (w < 4) {
            float a = 0.f;
#pragma unroll
            for (int q = 0; q < 16; q++) a += s_x[lane + 32 * q] * g_u2[w * 512 + lane + 32 * q];
            a = warp_sum(a);
            if (lane == 0) s_sA[w] = a + g_c2s[w];
        }
        __syncthreads();

        float c0 = 0.f, c1v = 0.f, c2v = 0.f, c3v = 0.f;
        for (int base = 0; base < cnt; base += CH2) {
            int mc = min(cnt - base, CH2);
            for (int e = t; e < mc; e += TPB)
                s_dst[e] = g_map[b * NN + g_l2dst[b * MAXL2 + base + e]] - 1;
            __syncthreads();

            for (int e = w; e < mc; e += 32) {
                const float* hr = g_hcat + ((size_t)b * MAXNODES + s_dst[e]) * 512;
                float hv[16];
#pragma unroll
                for (int q = 0; q < 16; q++) hv[q] = hr[lane + 32 * q];
                float a4[4];
#pragma unroll
                for (int h = 0; h < 4; h++) {
                    float a = 0.f;
#pragma unroll
                    for (int q = 0; q < 16; q++) a += hv[q] * g_v2[h * 512 + lane + 32 * q];
                    a4[h] = a;
                }
#pragma unroll
                for (int o = 16; o > 0; o >>= 1) {
#pragma unroll
                    for (int h = 0; h < 4; h++) a4[h] += __shfl_xor_sync(0xffffffffu, a4[h], o);
                }
                float sel = (lane == 0) ? a4[0] : (lane == 1) ? a4[1] : (lane == 2) ? a4[2] : a4[3];
                if (lane < 4) s_ev[e * 4 + lane] = lrelu_scale_exp(s_sA[lane] + sel + g_d2s[lane]);
            }
            __syncthreads();

            if (t < 512) {
#pragma unroll 8
                for (int e = 0; e < mc; e++) {
                    float x = g_hcat[((size_t)b * MAXNODES + s_dst[e]) * 512 + t];
                    c0  += s_ev[e * 4 + 0] * x;
                    c1v += s_ev[e * 4 + 1] * x;
                    c2v += s_ev[e * 4 + 2] * x;
                    c3v += s_ev[e * 4 + 3] * x;
                }
            } else if (w >= 28) {
                int h = w - 28;
                float r = 0.f;
                for (int e = lane; e < mc; e += 32) r += s_ev[e * 4 + h];
                r = warp_sum(r);
                if (lane == 0) s_rs[h] += r;
            }
            __syncthreads();
        }
        if (t < 512) {
            s_agg[0 * 512 + t] = c0;
            s_agg[1 * 512 + t] = c1v;
            s_agg[2 * 512 + t] = c2v;
            s_agg[3 * 512 + t] = c3v;
        }
        __syncthreads();

        // projection: 32 warps x 1 row = this block's 32-row slice
        {
            int r = chunk * 32 + w;
            int h = r >> 7;
            const float4* wr = (const float4*)(W2 + (size_t)r * 512);
            const float4* ag = (const float4*)(s_agg + h * 512);
            float a = 0.f;
#pragma unroll
            for (int q = 0; q < 4; q++) {
                float4 wv = wr[lane + 32 * q];
                float4 av = ag[lane + 32 * q];
                a += wv.x * av.x + wv.y * av.y + wv.z * av.z + wv.w * av.w;
            }
            a = warp_sum(a);
            if (lane == 0) {
                float rs = s_rs[h];
                float rsp = (rs == 0.f) ? 1.f : rs;
                g_p[b * 512 + r] = (a + rs * b2[r]) / rsp;
            }
        }

        __syncthreads();
        __threadfence();
        if (t == 0) atomicAdd((int*)&g_pc[b], 1);

        // ---------- head: blocks 0,1 spin for all 16 slices, then finish -----
        if (chunk == 0) {
            if (t == 0) { while (g_pc[b] < 16) { } }
            __syncthreads();
            __threadfence();

            float v = 0.f;
            if (t < 128) {
                const float* p = g_p + b * 512;
                v = 0.25f * (p[t] + p[128 + t] + p[256 + t] + p[384 + t]);
            }
            float sum = v, sumsq = v * v;
            block_sum2(sum, sumsq, s_red);
            float mn = sum * (1.f / 128.f);
            float var = (sumsq - 128.f * mn * mn) * (1.f / 127.f);
            var = fmaxf(var, 0.f);
            float stdv = sqrtf(var);
            float r0 = 0.f, r1 = 0.f;
            if (t < 128) {
                float y = g2[t] * (v - mn) / (stdv + LN_EPS) + bn2[t];
                float rr = (y > 0.f) ? y : 0.f;
                r0 = rr * Vw[t];
                r1 = rr * Vw[128 + t];
            }
            block_sum2(r0, r1, s_red);
            if (t == 0) {
                out[b * 2 + 0] = r0 + Vb[0];
                out[b * 2 + 1] = r1 + Vb[1];
            }
            // cleanup for next replay
            int nnr = min(g_nn[b], MAXNODES);
            for (int i = t; i < nnr; i += TPB) g_map[b * NN + g_nodes[b * MAXNODES + i]] = 0;
            __syncthreads();
            if (t == 0) { g_nn[b] = 0; g_c1[b] = 0; g_c2[b] = 0; g_pc[b] = 0; }
        }
    }

    // final arriver resets barrier state
    __threadfence();
    __syncthreads();
    if (t == 0) {
        if (atomicAdd(&g_done, 1) == GRID - 1) {
            g_bar = 0;
            atomicExch(&g_done, 0);
        }
    }
}

// ---------------- launch ----------------
extern "C" void kernel_launch(void* const* d_in, const int* in_sizes, int n_in,
                              void* d_out, int out_size) {
    const int* edge_in = (const int*)d_in[0];
    const int* edge_out = (const int*)d_in[1];
    const float* embed = (const float*)d_in[2];
    const float* W1 = (const float*)d_in[3];
    const float* b1 = (const float*)d_in[4];
    const float* a1 = (const float*)d_in[5];
    const float* g1 = (const float*)d_in[6];
    const float* bn1 = (const float*)d_in[7];
    const float* W2 = (const float*)d_in[8];
    const float* b2 = (const float*)d_in[9];
    const float* a2 = (const float*)d_in[10];
    const float* g2 = (const float*)d_in[11];
    const float* bn2 = (const float*)d_in[12];
    const float* Vw = (const float*)d_in[13];
    const float* Vb = (const float*)d_in[14];
    float* out = (float*)d_out;

    kAll<<<GRID, TPB>>>(edge_in, edge_out, embed, W1, b1, a1, g1, bn1,
                        W2, b2, a2, g2, bn2, Vw, Vb, out);
}

// round 16
// speedup vs baseline: 1.2702x; 1.2702x over previous
#include <cuda_runtime.h>
#include <math.h>

#define NB 2
#define NN 20001
#define NE 500000
#define MAXL2 4096
#define MAXNODES (MAXL2 + 1)
#define MAXE1 65536
#define MAXEPN 1024
#define CH2 1024
#define GRID 148
#define NFOLD 6
#define NSCAN (GRID - NFOLD)
#define TPB 512
#define NQ (NE / 4)            // int4s per src row = 125000
#define NG (NQ / 4)            // 4-int4 groups per batch = 31250
#define SCALEF 22.62741699796952f
#define INV_SCALEF (1.0f / 22.62741699796952f)
#define LN_EPS 1e-6f
#define ALPHA 0.2f

#define PF_L2(p) asm volatile("prefetch.global.L2 [%0];" :: "l"(p))

// ---------------- scratch (device globals; zero-init on load) ----------------
__device__ int   g_map[NB * NN];          // 0 = absent, -1 = inserting, else idx+1
__device__ int   g_nodes[NB * MAXNODES];
__device__ int   g_nn[NB];
__device__ int   g_c1[NB];
__device__ int   g_c2[NB];
__device__ volatile int g_bar;            // phase-counted grid barrier
__device__ int   g_done;
__device__ volatile int g_pc[NB];         // phase-3 projection completion count
__device__ int   g_l2dst[NB * MAXL2];
__device__ int   g_e1src[NB * MAXE1];
__device__ int   g_e1dst[NB * MAXE1];
__device__ float g_u1[4 * 256], g_v1[4 * 256], g_c1s[4], g_d1s[4];
__device__ float g_u2[4 * 512], g_v2[4 * 512], g_c2s[4], g_d2s[4];
__device__ float g_hcat[(size_t)NB * MAXNODES * 512];
__device__ float g_p[NB * 512];

// ---------------- helpers ----------------
__device__ __forceinline__ float warp_sum(float v) {
#pragma unroll
    for (int o = 16; o > 0; o >>= 1) v += __shfl_xor_sync(0xffffffffu, v, o);
    return v;
}

__device__ float block_sum(float v, float* sm) {
    int tid = threadIdx.x, w = tid >> 5, l = tid & 31, nw = blockDim.x >> 5;
    v = warp_sum(v);
    if (l == 0) sm[w] = v;
    __syncthreads();
    if (w == 0) {
        float r = (l < nw) ? sm[l] : 0.f;
        r = warp_sum(r);
        if (l == 0) sm[32] = r;
    }
    __syncthreads();
    float out = sm[32];
    __syncthreads();
    return out;
}

__device__ __forceinline__ float lrelu_scale_exp(float s) {
    float t = (s > 0.f) ? s : (ALPHA * s);
    return __expf(t * INV_SCALEF);
}

__device__ __forceinline__ void map_insert(int b, int node) {
    if (atomicCAS(&g_map[b * NN + node], 0, -1) == 0) {
        int q = atomicAdd(&g_nn[b], 1);
        if (q < MAXNODES) {
            g_nodes[b * MAXNODES + q] = node;
            g_map[b * NN + node] = q + 1;   // visible after fence + barrier
        }
    }
}

__device__ __forceinline__ void pf_embed_row(const float* embed, int node) {
    const float* er = embed + (size_t)node * 256;
#pragma unroll
    for (int q = 0; q < 8; q++) PF_L2(er + 32 * q);
}

// monotonic phase barrier: all GRID blocks co-resident (1 block/SM max)
__device__ __forceinline__ void grid_sync(int target) {
    __syncthreads();
    __threadfence();
    if (threadIdx.x == 0) {
        atomicAdd((int*)&g_bar, 1);
        while (g_bar < target) { }
    }
    __syncthreads();
}

// =================== THE kernel: everything in one launch ====================
__global__ void __launch_bounds__(TPB) kAll(
    const int* __restrict__ ei, const int* __restrict__ eo,
    const float* __restrict__ embed,
    const float* __restrict__ W1, const float* __restrict__ b1,
    const float* __restrict__ a1, const float* __restrict__ g1,
    const float* __restrict__ bn1,
    const float* __restrict__ W2, const float* __restrict__ b2,
    const float* __restrict__ a2, const float* __restrict__ g2,
    const float* __restrict__ bn2,
    const float* __restrict__ Vw, const float* __restrict__ Vb,
    float* __restrict__ out) {

    __shared__ int   s_dst[MAXEPN];
    __shared__ float s_ev[MAXEPN * 4];
    __shared__ __align__(16) float s_agg[2048];
    __shared__ float s_out[512];
    __shared__ float s_x[512];
    __shared__ float s_sA[4];
    __shared__ float s_rs[4];
    __shared__ float s_red[33];
    __shared__ int   s_m;

    int t = threadIdx.x, lane = t & 31, w = t >> 5;
    int bx = blockIdx.x;

    // ---------- phase 0: folds (last 6 blocks) || edge_out scan (rest) -------
    if (bx >= NSCAN) {
        int fg = (bx - NSCAN) * TPB + t;             // 0..3071
        if (fg < 1024) {
            int h = fg >> 8, k = fg & 255;
            float au = 0.f, av = 0.f;
#pragma unroll 16
            for (int j = 0; j < 128; j++) {
                float wv = W1[(h * 128 + j) * 256 + k];
                au += a1[h * 256 + j] * wv;
                av += a1[h * 256 + 128 + j] * wv;
            }
            g_u1[h * 256 + k] = au;
            g_v1[h * 256 + k] = av;
        } else if (fg < 3072) {
            int g2i = fg - 1024;
            int h = g2i >> 9, k = g2i & 511;
            float au = 0.f, av = 0.f;
#pragma unroll 16
            for (int j = 0; j < 128; j++) {
                float wv = W2[(h * 128 + j) * 512 + k];
                au += a2[h * 256 + j] * wv;
                av += a2[h * 256 + 128 + j] * wv;
            }
            g_u2[h * 512 + k] = au;
            g_v2[h * 512 + k] = av;
        }
        if (fg < 4) {
            int h = fg;
            float c1v = 0.f, d1v = 0.f, c2v = 0.f, d2v = 0.f;
            for (int j = 0; j < 128; j++) {
                c1v += a1[h * 256 + j] * b1[h * 128 + j];
                d1v += a1[h * 256 + 128 + j] * b1[h * 128 + j];
                c2v += a2[h * 256 + j] * b2[h * 128 + j];
                d2v += a2[h * 256 + 128 + j] * b2[h * 128 + j];
            }
            g_c1s[h] = c1v; g_d1s[h] = d1v; g_c2s[h] = c2v; g_d2s[h] = d2v;
        }
        if (fg < NB) {
            map_insert(fg, NN - 1);
            pf_embed_row(embed, NN - 1);
        }
    } else {
        // one-shot scan: each thread owns one group of 4 int4s (16 edges)
        int g = bx * TPB + t;                        // NB*NG = 62500 < 142*512
        if (g < NB * NG) {
            int b = (g >= NG) ? 1 : 0;
            int gg = g - b * NG;
            const int4* p = (const int4*)(eo + (size_t)(2 * b) * NE) + 4 * gg;
            int4 v0 = p[0], v1 = p[1], v2 = p[2], v3 = p[3];
            int base = gg * 16;
            const int* dstrow = eo + (size_t)(2 * b + 1) * NE;
            int sv[16] = {v0.x, v0.y, v0.z, v0.w, v1.x, v1.y, v1.z, v1.w,
                          v2.x, v2.y, v2.z, v2.w, v3.x, v3.y, v3.z, v3.w};
#pragma unroll
            for (int c = 0; c < 16; c++) {
                if (sv[c] == NN - 1) {
                    int dst = dstrow[base + c];
                    int pp = atomicAdd(&g_c2[b], 1);
                    if (pp < MAXL2) g_l2dst[b * MAXL2 + pp] = dst;
                    map_insert(b, dst);
                    pf_embed_row(embed, dst);    // warm L2 for layer-1
                }
            }
        }
    }

    grid_sync(1 * GRID);

    // ---------- phase 1: edge_in scan (all blocks, one group per thread) -----
    {
        int g = bx * TPB + t;
        if (g < NB * NG) {
            int b = (g >= NG) ? 1 : 0;
            int gg = g - b * NG;
            const int4* p = (const int4*)(ei + (size_t)(2 * b) * NE) + 4 * gg;
            int4 v0 = p[0], v1 = p[1], v2 = p[2], v3 = p[3];
            int base = gg * 16;
            const int* dstrow = ei + (size_t)(2 * b + 1) * NE;
            int sv[16] = {v0.x, v0.y, v0.z, v0.w, v1.x, v1.y, v1.z, v1.w,
                          v2.x, v2.y, v2.z, v2.w, v3.x, v3.y, v3.z, v3.w};
#pragma unroll
            for (int c = 0; c < 16; c++) {
                int m = g_map[b * NN + sv[c]];
                if (m > 0) {
                    int dst = dstrow[base + c];
                    int pp = atomicAdd(&g_c1[b], 1);
                    if (pp < MAXE1) {
                        g_e1src[b * MAXE1 + pp] = m - 1;
                        g_e1dst[b * MAXE1 + pp] = dst;
                    }
                    pf_embed_row(embed, dst);    // warm L2 for layer-1
                }
            }
        }
    }

    grid_sync(2 * GRID);

    // ---------- phase 2: layer-1, one block per node task ----------
    {
        int nnr0 = min(g_nn[0], MAXNODES);
        int nnr1 = min(g_nn[1], MAXNODES);
        int ntask = nnr0 + nnr1;
        for (int task = bx; task < ntask; task += GRID) {
            int b = (task >= nnr0) ? 1 : 0;
            int ln = task - b * nnr0;
            int cnt = min(g_c1[b], MAXE1);

            if (t == 0) s_m = 0;
            __syncthreads();
            for (int i = t; i < cnt; i += TPB)
                if (g_e1src[b * MAXE1 + i] == ln) {
                    int p = atomicAdd(&s_m, 1);
                    if (p < MAXEPN) s_dst[p] = g_e1dst[b * MAXE1 + i];
                }
            int node = g_nodes[b * MAXNODES + ln];
            if (t < 256) s_x[t] = embed[(size_t)node * 256 + t];
            __syncthreads();
            int m = min(s_m, MAXEPN);

            if (w < 4) {
                float a = 0.f;
#pragma unroll
                for (int q = 0; q < 8; q++) a += s_x[lane + 32 * q] * g_u1[w * 256 + lane + 32 * q];
                a = warp_sum(a);
                if (lane == 0) s_sA[w] = a + g_c1s[w];
            }
            __syncthreads();

            // pass 1: warp per edge (16 warps), 4-way interleaved butterflies
            for (int e = w; e < m; e += 16) {
                const float* er = embed + (size_t)s_dst[e] * 256;
                float emb[8];
#pragma unroll
                for (int q = 0; q < 8; q++) emb[q] = er[lane + 32 * q];
                float a4[4];
#pragma unroll
                for (int h = 0; h < 4; h++) {
                    float a = 0.f;
#pragma unroll
                    for (int q = 0; q < 8; q++) a += emb[q] * g_v1[h * 256 + lane + 32 * q];
                    a4[h] = a;
                }
#pragma unroll
                for (int o = 16; o > 0; o >>= 1) {
#pragma unroll
                    for (int h = 0; h < 4; h++) a4[h] += __shfl_xor_sync(0xffffffffu, a4[h], o);
                }
                float sel = (lane == 0) ? a4[0] : (lane == 1) ? a4[1] : (lane == 2) ? a4[2] : a4[3];
                if (lane < 4) s_ev[e * 4 + lane] = lrelu_scale_exp(s_sA[lane] + sel + g_d1s[lane]);
            }
            __syncthreads();

            // pass 2: t<256 feature-parallel agg (deep unroll); warps 12-15 rowsums
            if (t < 256) {
                float a0 = 0.f, a1v = 0.f, a2v = 0.f, a3v = 0.f;
#pragma unroll 16
                for (int e = 0; e < m; e++) {
                    float x = embed[(size_t)s_dst[e] * 256 + t];
                    a0  += s_ev[e * 4 + 0] * x;
                    a1v += s_ev[e * 4 + 1] * x;
                    a2v += s_ev[e * 4 + 2] * x;
                    a3v += s_ev[e * 4 + 3] * x;
                }
                s_agg[0 * 256 + t] = a0;
                s_agg[1 * 256 + t] = a1v;
                s_agg[2 * 256 + t] = a2v;
                s_agg[3 * 256 + t] = a3v;
            } else if (w >= 12) {
                int h = w - 12;
                float r = 0.f;
                for (int e = lane; e < m; e += 32) r += s_ev[e * 4 + h];
                r = warp_sum(r);
                if (lane == 0) s_rs[h] = r;
            }
            __syncthreads();

            // projection: 16 warps x 32 rows, float4 coalesced
#pragma unroll 8
            for (int i = 0; i < 32; i++) {
                int r = w + 16 * i;
                int h = r >> 7;
                const float4* wr = (const float4*)(W1 + (size_t)r * 256);
                const float4* ag = (const float4*)(s_agg + h * 256);
                float4 w0 = wr[lane], w1 = wr[lane + 32];
                float4 a0 = ag[lane], a1 = ag[lane + 32];
                float acc = w0.x * a0.x + w0.y * a0.y + w0.z * a0.z + w0.w * a0.w
                          + w1.x * a1.x + w1.y * a1.y + w1.z * a1.z + w1.w * a1.w;
                acc = warp_sum(acc);
                if (lane == 0) {
                    float rs = s_rs[h];
                    float rsp = (rs == 0.f) ? 1.f : rs;
                    s_out[r] = (acc + rs * b1[r]) / rsp;
                }
            }
            __syncthreads();

            // layernorm(512, ddof=1, eps on std) + elu
            float val = s_out[t];
            float tot = block_sum(val, s_red);
            float mn = tot * (1.f / 512.f);
            float dv = val - mn;
            float sq = block_sum(dv * dv, s_red);
            float stdv = sqrtf(sq * (1.f / 511.f));
            float y = g1[t] * dv / (stdv + LN_EPS) + bn1[t];
            g_hcat[((size_t)b * MAXNODES + ln) * 512 + t] = (y > 0.f) ? y : expm1f(y);
            __syncthreads();
        }
    }

    grid_sync(3 * GRID);

    // ---------- phase 3: layer-2 (blocks 0-31) + head via 16-count spin ------
    if (bx < 32) {
        int b = bx & 1;
        int chunk = bx >> 1;
        int cnt = min(g_c2[b], MAXL2);
        int ln0 = g_map[b * NN + (NN - 1)] - 1;
        if (ln0 < 0) ln0 = 0;

        s_x[t] = g_hcat[((size_t)b * MAXNODES + ln0) * 512 + t];
        if (t < 4) s_rs[t] = 0.f;
        __syncthreads();

        if (w < 4) {
            float a = 0.f;
#pragma unroll
            for (int q = 0; q < 16; q++) a += s_x[lane + 32 * q] * g_u2[w * 512 + lane + 32 * q];
            a = warp_sum(a);
            if (lane == 0) s_sA[w] = a + g_c2s[w];
        }
        __syncthreads();

        float c0 = 0.f, c1v = 0.f, c2v = 0.f, c3v = 0.f;
        for (int base = 0; base < cnt; base += CH2) {
            int mc = min(cnt - base, CH2);
            for (int e = t; e < mc; e += TPB)
                s_dst[e] = g_map[b * NN + g_l2dst[b * MAXL2 + base + e]] - 1;
            __syncthreads();

            for (int e = w; e < mc; e += 16) {
                const float* hr = g_hcat + ((size_t)b * MAXNODES + s_dst[e]) * 512;
                float hv[16];
#pragma unroll
                for (int q = 0; q < 16; q++) hv[q] = hr[lane + 32 * q];
                float a4[4];
#pragma unroll
                for (int h = 0; h < 4; h++) {
                    float a = 0.f;
#pragma unroll
                    for (int q = 0; q < 16; q++) a += hv[q] * g_v2[h * 512 + lane + 32 * q];
                    a4[h] = a;
                }
#pragma unroll
                for (int o = 16; o > 0; o >>= 1) {
#pragma unroll
                    for (int h = 0; h < 4; h++) a4[h] += __shfl_xor_sync(0xffffffffu, a4[h], o);
                }
                float sel = (lane == 0) ? a4[0] : (lane == 1) ? a4[1] : (lane == 2) ? a4[2] : a4[3];
                if (lane < 4) s_ev[e * 4 + lane] = lrelu_scale_exp(s_sA[lane] + sel + g_d2s[lane]);
            }
            __syncthreads();

            if (w >= 12) {
                int h = w - 12;
                float r = 0.f;
                for (int e = lane; e < mc; e += 32) r += s_ev[e * 4 + h];
                r = warp_sum(r);
                if (lane == 0) s_rs[h] += r;
            }
#pragma unroll 16
            for (int e = 0; e < mc; e++) {
                float x = g_hcat[((size_t)b * MAXNODES + s_dst[e]) * 512 + t];
                c0  += s_ev[e * 4 + 0] * x;
                c1v += s_ev[e * 4 + 1] * x;
                c2v += s_ev[e * 4 + 2] * x;
                c3v += s_ev[e * 4 + 3] * x;
            }
            __syncthreads();
        }
        s_agg[0 * 512 + t] = c0;
        s_agg[1 * 512 + t] = c1v;
        s_agg[2 * 512 + t] = c2v;
        s_agg[3 * 512 + t] = c3v;
        __syncthreads();

        // projection: 16 warps x 2 rows = this block's 32-row slice
#pragma unroll
        for (int i = 0; i < 2; i++) {
            int r = chunk * 32 + w + 16 * i;
            int h = r >> 7;
            const float4* wr = (const float4*)(W2 + (size_t)r * 512);
            const float4* ag = (const float4*)(s_agg + h * 512);
            float a = 0.f;
#pragma unroll
            for (int q = 0; q < 4; q++) {
                float4 wv = wr[lane + 32 * q];
                float4 av = ag[lane + 32 * q];
                a += wv.x * av.x + wv.y * av.y + wv.z * av.z + wv.w * av.w;
            }
            a = warp_sum(a);
            if (lane == 0) {
                float rs = s_rs[h];
                float rsp = (rs == 0.f) ? 1.f : rs;
                g_p[b * 512 + r] = (a + rs * b2[r]) / rsp;
            }
        }

        // signal projection slice done
        __syncthreads();
        __threadfence();
        if (t == 0) atomicAdd((int*)&g_pc[b], 1);

        // ---------- head: blocks 0,1 spin for all 16 slices, then finish -----
        if (chunk == 0) {
            if (t == 0) { while (g_pc[b] < 16) { } }
            __syncthreads();
            __threadfence();

            float v = 0.f;
            if (t < 128) {
                const float* p = g_p + b * 512;
                v = 0.25f * (p[t] + p[128 + t] + p[256 + t] + p[384 + t]);
            }
            float tot = block_sum((t < 128) ? v : 0.f, s_red);
            float mn = tot * (1.f / 128.f);
            float dv = (t < 128) ? (v - mn) : 0.f;
            float sq = block_sum(dv * dv, s_red);
            float stdv = sqrtf(sq * (1.f / 127.f));
            float r0 = 0.f, r1 = 0.f;
            if (t < 128) {
                float y = g2[t] * dv / (stdv + LN_EPS) + bn2[t];
                float rr = (y > 0.f) ? y : 0.f;
                r0 = rr * Vw[t];
                r1 = rr * Vw[128 + t];
            }
            float o0 = block_sum(r0, s_red);
            float o1 = block_sum(r1, s_red);
            if (t == 0) {
                out[b * 2 + 0] = o0 + Vb[0];
                out[b * 2 + 1] = o1 + Vb[1];
            }
            // cleanup for next replay
            int nnr = min(g_nn[b], MAXNODES);
            for (int i = t; i < nnr; i += TPB) g_map[b * NN + g_nodes[b * MAXNODES + i]] = 0;
            __syncthreads();
            if (t == 0) { g_nn[b] = 0; g_c1[b] = 0; g_c2[b] = 0; g_pc[b] = 0; }
        }
    }

    // all blocks have passed their last g_bar spin; final arriver resets state.
    __threadfence();
    __syncthreads();
    if (t == 0) {
        if (atomicAdd(&g_done, 1) == GRID - 1) {
            g_bar = 0;
            atomicExch(&g_done, 0);
        }
    }
}

// ---------------- launch ----------------
extern "C" void kernel_launch(void* const* d_in, const int* in_sizes, int n_in,
                              void* d_out, int out_size) {
    const int* edge_in = (const int*)d_in[0];
    const int* edge_out = (const int*)d_in[1];
    const float* embed = (const float*)d_in[2];
    const float* W1 = (const float*)d_in[3];
    const float* b1 = (const float*)d_in[4];
    const float* a1 = (const float*)d_in[5];
    const float* g1 = (const float*)d_in[6];
    const float* bn1 = (const float*)d_in[7];
    const float* W2 = (const float*)d_in[8];
    const float* b2 = (const float*)d_in[9];
    const float* a2 = (const float*)d_in[10];
    const float* g2 = (const float*)d_in[11];
    const float* bn2 = (const float*)d_in[12];
    const float* Vw = (const float*)d_in[13];
    const float* Vb = (const float*)d_in[14];
    float* out = (float*)d_out;

    kAll<<<GRID, TPB>>>(edge_in, edge_out, embed, W1, b1, a1, g1, bn1,
                        W2, b2, a2, g2, bn2, Vw, Vb, out);
}